// round 14
// baseline (speedup 1.0000x reference)
#include <cuda_runtime.h>
#include <cuda_fp16.h>
#include <math.h>
#include <stdint.h>

#define T_STEPS 160
#define BATCH   640
#define FDIM    40
#define HDIM    768
#define PJDIM   256
#define NBLK    120

#define NCH0    5      // gates L0: K=296 padded to 320, chunks of 64
#define NCH12   8      // gates L1/2: K=512
#define NCHP    12     // proj: K=768
#define K0REAL  296

// ---------------- device globals ----------------------------------------------
__device__ float  g_c[3][HDIM * BATCH];     // fp32 cell, permuted [gc*640+row]
__device__ __half g_m[3][HDIM * BATCH];     // fp16 m, permuted [gc*640+row]
__device__ __half g_hh[3][BATCH * PJDIM];   // fp16 h, row-major
__device__ float  g_h[3][BATCH * PJDIM];    // fp32 h (final norm)
__device__ unsigned g_bar_count;
__device__ unsigned g_bar_gen;

// Pre-swizzled fp16 weights, gmem order == smem order (paired-k LDS.128 layout).
// gates chunk = 8192 u32 words; proj chunk = 2048 u32 words.
__device__ uint32_t g_W0pre[12 * NCH0  * 8192];
__device__ uint32_t g_W1pre[12 * NCH12 * 8192];
__device__ uint32_t g_W2pre[12 * NCH12 * 8192];
__device__ uint32_t g_Ppre [3 * 4 * NCHP * 2048];

__device__ __forceinline__ float sig_fast(float x) {
    float e = __expf(-x);
    float r; asm("rcp.approx.f32 %0, %1;" : "=f"(r) : "f"(1.0f + e));
    return r;
}
__device__ __forceinline__ float tanh_fast(float x) {
    float e = __expf(-2.0f * x);
    float r; asm("rcp.approx.f32 %0, %1;" : "=f"(r) : "f"(1.0f + e));
    return 2.0f * r - 1.0f;
}

__device__ __forceinline__ uint32_t f2h2(float a, float b) {
    __half2 h = __floats2half2_rn(a, b);
    return *(uint32_t*)&h;
}

__device__ __forceinline__ void mma_f16(float& c0, float& c1, float& c2, float& c3,
                                        uint32_t a0, uint32_t a1, uint32_t a2, uint32_t a3,
                                        uint32_t b0, uint32_t b1) {
    asm("mma.sync.aligned.m16n8k16.row.col.f32.f16.f16.f32 "
        "{%0,%1,%2,%3},{%4,%5,%6,%7},{%8,%9},{%0,%1,%2,%3};"
        : "+f"(c0), "+f"(c1), "+f"(c2), "+f"(c3)
        : "r"(a0), "r"(a1), "r"(a2), "r"(a3), "r"(b0), "r"(b1));
}

__device__ __forceinline__ void cp16(uint32_t dst, const void* src) {
    asm volatile("cp.async.cg.shared.global [%0], [%1], 16;" :: "r"(dst), "l"(src));
}
#define CP_COMMIT() asm volatile("cp.async.commit_group;")
#define CP_WAIT0()  asm volatile("cp.async.wait_group 0;" ::: "memory")
#define CP_WAIT1()  asm volatile("cp.async.wait_group 1;" ::: "memory")

__device__ __forceinline__ void grid_barrier() {
    __syncthreads();
    if (threadIdx.x == 0) {
        __threadfence();
        unsigned gen = *(volatile unsigned*)&g_bar_gen;
        if (atomicAdd(&g_bar_count, 1u) == NBLK - 1) {
            g_bar_count = 0;
            __threadfence();
            atomicAdd(&g_bar_gen, 1u);
        } else {
            while (*(volatile unsigned*)&g_bar_gen == gen) { __nanosleep(64); }
        }
        __threadfence();
    }
    __syncthreads();
}

// ---------------- weight precompute --------------------------------------------
// Paired-k layout word (within chunk): u = word>>2, w4 = word&3
//   gates: sp = u>>10, col = (u>>2)&255, qx = u&3
//   q = qx ^ ((col>>1)&3); sbit = w4>>1; hi = w4&1
//   k = ch*64 + (sp*2+sbit)*16 + 2*(q + 4*hi); u32 = halves (k, k+1)
__device__ void prep_w(uint32_t* dst, const float* W, long idx, int NCH, int K) {
    int nt = (int)(idx / ((long)NCH * 8192));
    int r  = (int)(idx % ((long)NCH * 8192));
    int ch = r / 8192, g = r % 8192;
    int u = g >> 2, w4 = g & 3;
    int sp = u >> 10, col = (u >> 2) & 255, qx = u & 3;
    int q = qx ^ ((col >> 1) & 3);
    int k = ch * 64 + (sp * 2 + (w4 >> 1)) * 16 + 2 * (q + 4 * (w4 & 1));
    int gate = col & 3;
    int wcol = gate * HDIM + nt * 64 + (col >> 2);
    float lo = (k     < K) ? W[(size_t)k * (4 * HDIM) + wcol] : 0.0f;
    float hf = (k + 1 < K) ? W[(size_t)(k + 1) * (4 * HDIM) + wcol] : 0.0f;
    dst[idx] = f2h2(lo, hf);
}

__global__ void precompute_weights(const float* __restrict__ W0, const float* __restrict__ W1,
                                   const float* __restrict__ W2, const float* __restrict__ P0,
                                   const float* __restrict__ P1, const float* __restrict__ P2)
{
    long idx = (long)blockIdx.x * 256 + threadIdx.x;
    const long NW0  = 12L * NCH0  * 8192;
    const long NW12 = 12L * NCH12 * 8192;
    if (idx < NW0)  { prep_w(g_W0pre, W0, idx, NCH0, K0REAL); return; }
    idx -= NW0;
    if (idx < NW12) { prep_w(g_W1pre, W1, idx, NCH12, 512); return; }
    idx -= NW12;
    if (idx < NW12) { prep_w(g_W2pre, W2, idx, NCH12, 512); return; }
    idx -= NW12;
    if (idx < 3L * 4 * NCHP * 2048) {
        long save = idx;
        int layer = (int)(idx / (4 * NCHP * 2048));
        int r  = (int)(idx % (4 * NCHP * 2048));
        int nt4 = r / (NCHP * 2048);
        int r2  = r % (NCHP * 2048);
        int ch  = r2 / 2048, g = r2 % 2048;
        int u = g >> 2, w4 = g & 3;
        int sp = u >> 8, col = (u >> 2) & 63, qx = u & 3;
        int q = qx ^ ((col >> 1) & 3);
        int k = ch * 64 + (sp * 2 + (w4 >> 1)) * 16 + 2 * (q + 4 * (w4 & 1));
        int n = nt4 * 64 + col;
        const float* P = (layer == 0) ? P0 : (layer == 1) ? P1 : P2;
        g_Ppre[save] = f2h2(P[k * PJDIM + n], P[(k + 1) * PJDIM + n]);
    }
}

// ---------------- gates: 64x256 tile, paired-k LDS.128 frags --------------------
// smem words: A bufs 3x2048 at [0,6144), W bufs 3x8192 at [6144, 30720)
template <int XK, int NCH>
__device__ void gates_tile(const float* __restrict__ xA,
                           const __half* __restrict__ h1,
                           const __half* __restrict__ h2,
                           const uint32_t* __restrict__ Wt,
                           const float* __restrict__ bias,
                           float* __restrict__ cbuf, __half* __restrict__ mbuf,
                           uint32_t* __restrict__ sm, uint32_t sb)
{
    const int tid = threadIdx.x, lane = tid & 31, wid = tid >> 5;
    const int bid = blockIdx.x;
    const int m0  = (bid % 10) * 64;
    const int nt0 = bid / 10;
    const int wm = wid >> 2, wn = wid & 3;
    const int grp = lane >> 2, q = lane & 3;
    const int qx4 = ((lane & 3) ^ ((lane >> 3) & 3)) * 4;  // (q ^ ((grp>>1)&3))*4
    const int row = tid >> 2, aj = tid & 3;
    const int xs  = (row >> 1) & 3;

    float acc[2][8][4];
#pragma unroll
    for (int mt = 0; mt < 2; mt++)
#pragma unroll
        for (int nt = 0; nt < 8; nt++)
#pragma unroll
            for (int r = 0; r < 4; r++) acc[mt][nt][r] = 0.0f;

    uint4 hv0, hv1;
    auto ld8 = [&](int kg) -> uint4 {
        uint4 v;
        if (XK == 40) {
            if (kg < 40) {
                float4 f0 = __ldg((const float4*)&xA[(m0 + row) * 40 + kg]);
                float4 f1 = __ldg((const float4*)&xA[(m0 + row) * 40 + kg + 4]);
                v.x = f2h2(f0.x, f0.y); v.y = f2h2(f0.z, f0.w);
                v.z = f2h2(f1.x, f1.y); v.w = f2h2(f1.z, f1.w);
            } else if (kg < 296) {
                v = __ldcg((const uint4*)&h2[(m0 + row) * PJDIM + kg - 40]);
            } else {
                v = make_uint4(0u, 0u, 0u, 0u);
            }
        } else {
            if (kg < 256) v = __ldcg((const uint4*)&h1[(m0 + row) * PJDIM + kg]);
            else          v = __ldcg((const uint4*)&h2[(m0 + row) * PJDIM + kg - 256]);
        }
        return v;
    };
    auto ldA = [&](int ch) {
        hv0 = ld8(ch * 64 + aj * 8);
        hv1 = ld8(ch * 64 + aj * 8 + 32);
    };
    // store 4 u32 pairs: word = row*16 + ((j^xs)<<2) + (aj>>1)*2 + (aj&1); hv1 at +1024
    auto stA = [&](int buf) {
        uint32_t* d0 = sm + buf * 2048 + row * 16 + (aj >> 1) * 2 + (aj & 1);
        d0[(0 ^ xs) << 2] = hv0.x; d0[(1 ^ xs) << 2] = hv0.y;
        d0[(2 ^ xs) << 2] = hv0.z; d0[(3 ^ xs) << 2] = hv0.w;
        uint32_t* d1 = d0 + 1024;
        d1[(0 ^ xs) << 2] = hv1.x; d1[(1 ^ xs) << 2] = hv1.y;
        d1[(2 ^ xs) << 2] = hv1.z; d1[(3 ^ xs) << 2] = hv1.w;
    };
    auto ldW = [&](int ch, int buf) {
        const uint32_t* src = Wt + (size_t)ch * 8192 + tid * 4;
        uint32_t dst = sb + (6144 + buf * 8192 + tid * 4) * 4;
#pragma unroll
        for (int e = 0; e < 8; e++) cp16(dst + e * 4096, src + e * 1024);
        CP_COMMIT();
    };

    // prologue: prefetch chunks 0 and 1
    ldA(0); stA(0); ldW(0, 0);
    ldA(1); stA(1); ldW(1, 1);

    for (int ch = 0; ch < NCH; ch++) {
        int buf = ch % 3;
        bool more = (ch + 2 < NCH);
        if (more) ldA(ch + 2);                 // LDG overlaps the cp wait
        if (ch <= NCH - 2) CP_WAIT1(); else CP_WAIT0();
        __syncthreads();

        const uint32_t* bA = sm + buf * 2048;
        const uint32_t* bW = sm + 6144 + buf * 8192;
#pragma unroll
        for (int sp = 0; sp < 2; sp++) {
            uint4 A0[2], A1[2];
#pragma unroll
            for (int mt = 0; mt < 2; mt++) {
                int r0 = wm * 32 + mt * 16 + grp;
                A0[mt] = *(const uint4*)&bA[sp * 1024 + r0 * 16 + qx4];
                A1[mt] = *(const uint4*)&bA[sp * 1024 + (r0 + 8) * 16 + qx4];
            }
#pragma unroll
            for (int nt = 0; nt < 8; nt++) {
                int col = wn * 64 + nt * 8 + grp;
                uint4 B = *(const uint4*)&bW[sp * 4096 + col * 16 + qx4];
#pragma unroll
                for (int mt = 0; mt < 2; mt++)
                    mma_f16(acc[mt][nt][0], acc[mt][nt][1], acc[mt][nt][2], acc[mt][nt][3],
                            A0[mt].x, A1[mt].x, A0[mt].y, A1[mt].y, B.x, B.y);
#pragma unroll
                for (int mt = 0; mt < 2; mt++)
                    mma_f16(acc[mt][nt][0], acc[mt][nt][1], acc[mt][nt][2], acc[mt][nt][3],
                            A0[mt].z, A1[mt].z, A0[mt].w, A1[mt].w, B.z, B.w);
            }
        }
        if (more) { stA((ch + 2) % 3); ldW(ch + 2, (ch + 2) % 3); }
    }

    // Epilogue: lane pair (lane^1) assembles (i,j,f,o) per cell column.
    const int gc0 = nt0 * 64;
    const int p = lane & 1;
#pragma unroll
    for (int nt = 0; nt < 8; nt++) {
        int cc = wn * 16 + 2 * nt + (q >> 1);
        int gc = gc0 + cc;
        float bi = __ldg(&bias[gc]);
        float bj = __ldg(&bias[gc + HDIM]);
        float bf = __ldg(&bias[gc + 2 * HDIM]);
        float bo = __ldg(&bias[gc + 3 * HDIM]);
#pragma unroll
        for (int mt = 0; mt < 2; mt++) {
            float c0 = acc[mt][nt][0], c1 = acc[mt][nt][1];
            float c2 = acc[mt][nt][2], c3 = acc[mt][nt][3];
            float v = __shfl_xor_sync(0xffffffffu, p ? c0 : c2, 1);
            float w = __shfl_xor_sync(0xffffffffu, p ? c1 : c3, 1);
            float zi, zj, zf, zo;
            if (p == 0) { zi = c0; zj = c1; zf = v;  zo = w;  }
            else        { zi = v;  zj = w;  zf = c2; zo = c3; }
            int rowE = m0 + wm * 32 + mt * 16 + grp + (p ? 8 : 0);
            zi += bi; zj += bj; zf += bf; zo += bo;
            float cold = cbuf[gc * BATCH + rowE];
            float cn = sig_fast(zf + 1.0f) * cold + sig_fast(zi) * tanh_fast(zj);
            float mm = sig_fast(zo) * tanh_fast(cn);
            cbuf[gc * BATCH + rowE] = cn;
            mbuf[gc * BATCH + rowE] = __float2half(mm);
        }
    }
}

// ---------------- projection: 64x64 tile; A = R13 layout, B = paired LDS.128 ----
// smem words: A bufs 3x2048 at [0,6144), W bufs 3x2048 at [6144,12288)
__device__ void proj_mma(const __half* __restrict__ mperm,
                         const uint32_t* __restrict__ Pblk,
                         float* __restrict__ hL, __half* __restrict__ hhL,
                         int m0, int nt4,
                         uint32_t* __restrict__ sm, uint32_t sb)
{
    const int tid = threadIdx.x, lane = tid & 31, wid = tid >> 5;
    const int wm = wid >> 2, wn = wid & 3;
    const int grp = lane >> 2, q = lane & 3;
    const int qx4 = ((lane & 3) ^ ((lane >> 3) & 3)) * 4;
    const int klocal = tid >> 3;           // 0..31
    const int row8 = (tid & 7) * 8;

    float acc[2][2][4];
#pragma unroll
    for (int mt = 0; mt < 2; mt++)
#pragma unroll
        for (int nt = 0; nt < 2; nt++)
#pragma unroll
            for (int r = 0; r < 4; r++) acc[mt][nt][r] = 0.0f;

    uint4 hv0, hv1;
    auto ldA = [&](int ch) {
        hv0 = __ldcg((const uint4*)&mperm[(ch * 64 + klocal) * BATCH + m0 + row8]);
        hv1 = __ldcg((const uint4*)&mperm[(ch * 64 + klocal + 32) * BATCH + m0 + row8]);
    };
    auto stA = [&](int buf) {   // R13 layout: word = s*512 + row*8 + pos^xr
#pragma unroll
        for (int set = 0; set < 2; set++) {
            int kl = klocal + set * 32;
            int kw = kl >> 1, hsel = kl & 1;
            int s = kw >> 3, kw8 = kw & 7;
            int pos = (kw8 & 3) * 2 + (kw8 >> 2);
            uint4 hvv = set ? hv1 : hv0;
            __half hs[8];
            *(uint32_t*)&hs[0] = hvv.x; *(uint32_t*)&hs[2] = hvv.y;
            *(uint32_t*)&hs[4] = hvv.z; *(uint32_t*)&hs[6] = hvv.w;
#pragma unroll
            for (int e = 0; e < 8; e++) {
                int rw = row8 + e;
                int xr = ((rw >> 3) & 3) << 1;
                __half* hp = (__half*)(sm + buf * 2048 + s * 512 + rw * 8 + (pos ^ xr));
                hp[hsel] = hs[e];
            }
        }
    };
    auto ldW = [&](int ch, int buf) {
        const uint32_t* src = Pblk + (size_t)ch * 2048 + tid * 4;
        uint32_t dst = sb + (6144 + buf * 2048 + tid * 4) * 4;
        cp16(dst, src);
        cp16(dst + 4096, src + 1024);
        CP_COMMIT();
    };

    ldA(0); stA(0); ldW(0, 0);
    ldA(1); stA(1); ldW(1, 1);

    for (int ch = 0; ch < NCHP; ch++) {
        int buf = ch % 3;
        bool more = (ch + 2 < NCHP);
        if (more) ldA(ch + 2);
        if (ch <= NCHP - 2) CP_WAIT1(); else CP_WAIT0();
        __syncthreads();

        const uint32_t* bA = sm + buf * 2048;
        const uint32_t* bW = sm + 6144 + buf * 2048;
#pragma unroll
        for (int sp = 0; sp < 2; sp++) {
            uint4 Bn[2];
#pragma unroll
            for (int nt = 0; nt < 2; nt++) {
                int col = wn * 16 + nt * 8 + grp;
                Bn[nt] = *(const uint4*)&bW[sp * 1024 + col * 16 + qx4];
            }
#pragma unroll
            for (int s01 = 0; s01 < 2; s01++) {
                int s = sp * 2 + s01;
                uint2 a02[2], a13[2];
#pragma unroll
                for (int mt = 0; mt < 2; mt++) {
                    int r0 = wm * 32 + mt * 16 + grp;
                    int r1 = r0 + 8;
                    int x0 = ((r0 >> 3) & 3) << 1;
                    int x1 = ((r1 >> 3) & 3) << 1;
                    a02[mt] = *(const uint2*)&bA[s * 512 + r0 * 8 + ((q * 2) ^ x0)];
                    a13[mt] = *(const uint2*)&bA[s * 512 + r1 * 8 + ((q * 2) ^ x1)];
                }
#pragma unroll
                for (int nt = 0; nt < 2; nt++) {
                    uint32_t b0 = s01 ? Bn[nt].z : Bn[nt].x;
                    uint32_t b1 = s01 ? Bn[nt].w : Bn[nt].y;
#pragma unroll
                    for (int mt = 0; mt < 2; mt++)
                        mma_f16(acc[mt][nt][0], acc[mt][nt][1], acc[mt][nt][2], acc[mt][nt][3],
                                a02[mt].x, a13[mt].x, a02[mt].y, a13[mt].y, b0, b1);
                }
            }
        }
        if (more) { stA((ch + 2) % 3); ldW(ch + 2, (ch + 2) % 3); }
    }

#pragma unroll
    for (int mt = 0; mt < 2; mt++)
#pragma unroll
        for (int nt = 0; nt < 2; nt++) {
            int rw = m0 + wm * 32 + mt * 16 + grp;
            int col = nt4 * 64 + wn * 16 + nt * 8 + 2 * q;
            *(float2*)&hL[rw * PJDIM + col] = make_float2(acc[mt][nt][0], acc[mt][nt][1]);
            *(float2*)&hL[(rw + 8) * PJDIM + col] = make_float2(acc[mt][nt][2], acc[mt][nt][3]);
            *(uint32_t*)&hhL[rw * PJDIM + col] = f2h2(acc[mt][nt][0], acc[mt][nt][1]);
            *(uint32_t*)&hhL[(rw + 8) * PJDIM + col] = f2h2(acc[mt][nt][2], acc[mt][nt][3]);
        }
}

// ---------------- persistent driver ----------------------------------------------
__global__ void __launch_bounds__(256, 1)
lstm_persistent(const float* __restrict__ x,
                const float* __restrict__ b0, const float* __restrict__ b1,
                const float* __restrict__ b2, float* __restrict__ out)
{
    extern __shared__ uint32_t dynsmem[];   // 30720 words = 120KB
    __shared__ float red[8];
    uint32_t* sm = dynsmem;
    uint32_t sb = (uint32_t)__cvta_generic_to_shared(dynsmem);

    const int bid = blockIdx.x;
    const int tid = threadIdx.x;

    for (int i = bid * 256 + tid; i < 3 * HDIM * BATCH; i += NBLK * 256)
        ((float*)g_c)[i] = 0.0f;
    for (int i = bid * 256 + tid; i < 3 * BATCH * PJDIM / 2; i += NBLK * 256)
        ((uint32_t*)g_hh)[i] = 0u;
    for (int i = bid * 256 + tid; i < 3 * BATCH * PJDIM; i += NBLK * 256)
        ((float*)g_h)[i] = 0.0f;
    grid_barrier();

    const int g_nt = bid / 10;
    const uint32_t* W0t = g_W0pre + (size_t)g_nt * NCH0  * 8192;
    const uint32_t* W1t = g_W1pre + (size_t)g_nt * NCH12 * 8192;
    const uint32_t* W2t = g_W2pre + (size_t)g_nt * NCH12 * 8192;

    const int p_layer = bid / 40, p_rem = bid % 40;
    const int p_m0 = (p_rem % 10) * 64, p_nt4 = p_rem / 10;
    const uint32_t* Pblk = g_Ppre + ((size_t)p_layer * 4 + p_nt4) * NCHP * 2048;

    for (int s = 0; s < T_STEPS + 2; s++) {
        if (s < T_STEPS)
            gates_tile<40, NCH0>(x + (size_t)s * BATCH * FDIM, (const __half*)nullptr,
                                 g_hh[0], W0t, b0, g_c[0], g_m[0], sm, sb);
        if (s >= 1 && s - 1 < T_STEPS)
            gates_tile<256, NCH12>(nullptr, g_hh[0], g_hh[1], W1t, b1,
                                   g_c[1], g_m[1], sm, sb);
        if (s >= 2 && s - 2 < T_STEPS)
            gates_tile<256, NCH12>(nullptr, g_hh[1], g_hh[2], W2t, b2,
                                   g_c[2], g_m[2], sm, sb);
        grid_barrier();

        if (s - p_layer >= 0 && s - p_layer < T_STEPS)
            proj_mma(g_m[p_layer], Pblk, g_h[p_layer], g_hh[p_layer],
                     p_m0, p_nt4, sm, sb);
        grid_barrier();
    }

    for (int b = bid; b < BATCH; b += NBLK) {
        float v = __ldcg(&g_h[2][b * PJDIM + tid]);
        float sm2 = v * v;
#pragma unroll
        for (int o = 16; o > 0; o >>= 1) sm2 += __shfl_xor_sync(0xffffffffu, sm2, o);
        if ((tid & 31) == 0) red[tid >> 5] = sm2;
        __syncthreads();
        float tot = red[0] + red[1] + red[2] + red[3] +
                    red[4] + red[5] + red[6] + red[7];
        out[b * PJDIM + tid] = v * rsqrtf(fmaxf(tot, 1e-12f));
        __syncthreads();
    }
}

extern "C" void kernel_launch(void* const* d_in, const int* in_sizes, int n_in,
                              void* d_out, int out_size)
{
    const float* x  = (const float*)d_in[0];
    const float* W0 = (const float*)d_in[1];
    const float* b0 = (const float*)d_in[2];
    const float* P0 = (const float*)d_in[3];
    const float* W1 = (const float*)d_in[4];
    const float* b1 = (const float*)d_in[5];
    const float* P1 = (const float*)d_in[6];
    const float* W2 = (const float*)d_in[7];
    const float* b2 = (const float*)d_in[8];
    const float* P2 = (const float*)d_in[9];
    float* out = (float*)d_out;
    (void)in_sizes; (void)n_in; (void)out_size;

    static int attr_done = 0;
    if (!attr_done) {
        cudaFuncSetAttribute(lstm_persistent,
                             cudaFuncAttributeMaxDynamicSharedMemorySize, 122880);
        attr_done = 1;
    }

    // total u32 words: 491520 + 2*786432 + 294912 = 2,359,296 -> 9216 blocks @256
    precompute_weights<<<9216, 256>>>(W0, W1, W2, P0, P1, P2);
    lstm_persistent<<<NBLK, 256, 122880>>>(x, b0, b1, b2, out);
}

// round 15
// speedup vs baseline: 1.2072x; 1.2072x over previous
#include <cuda_runtime.h>
#include <cuda_fp16.h>
#include <math.h>
#include <stdint.h>

#define T_STEPS 160
#define BATCH   640
#define FDIM    40
#define HDIM    768
#define PJDIM   256
#define NBLK    120
#define NTHR    512

#define NCH0    5      // gates L0: K=296 padded to 320, chunks of 64
#define NCH12   8      // gates L1/2: K=512
#define NCHP    12     // proj: K=768
#define K0REAL  296

// ---------------- device globals ----------------------------------------------
__device__ float  g_c[3][HDIM * BATCH];     // fp32 cell, permuted [gc*640+row]
__device__ __half g_m[3][HDIM * BATCH];     // fp16 m, permuted [gc*640+row]
__device__ __half g_hh[3][BATCH * PJDIM];   // fp16 h, row-major
__device__ float  g_h[3][BATCH * PJDIM];    // fp32 h (final norm)
__device__ unsigned g_bar_count;
__device__ unsigned g_bar_gen;

// Pre-swizzled fp16 weights, gmem order == smem order (paired-k LDS.128 layout).
__device__ uint32_t g_W0pre[12 * NCH0  * 8192];
__device__ uint32_t g_W1pre[12 * NCH12 * 8192];
__device__ uint32_t g_W2pre[12 * NCH12 * 8192];
__device__ uint32_t g_Ppre [3 * 4 * NCHP * 2048];

__device__ __forceinline__ float sig_fast(float x) {
    float e = __expf(-x);
    float r; asm("rcp.approx.f32 %0, %1;" : "=f"(r) : "f"(1.0f + e));
    return r;
}
__device__ __forceinline__ float tanh_fast(float x) {
    float e = __expf(-2.0f * x);
    float r; asm("rcp.approx.f32 %0, %1;" : "=f"(r) : "f"(1.0f + e));
    return 2.0f * r - 1.0f;
}

__device__ __forceinline__ uint32_t f2h2(float a, float b) {
    __half2 h = __floats2half2_rn(a, b);
    return *(uint32_t*)&h;
}

__device__ __forceinline__ void mma_f16(float& c0, float& c1, float& c2, float& c3,
                                        uint32_t a0, uint32_t a1, uint32_t a2, uint32_t a3,
                                        uint32_t b0, uint32_t b1) {
    asm("mma.sync.aligned.m16n8k16.row.col.f32.f16.f16.f32 "
        "{%0,%1,%2,%3},{%4,%5,%6,%7},{%8,%9},{%0,%1,%2,%3};"
        : "+f"(c0), "+f"(c1), "+f"(c2), "+f"(c3)
        : "r"(a0), "r"(a1), "r"(a2), "r"(a3), "r"(b0), "r"(b1));
}

__device__ __forceinline__ void cp16(uint32_t dst, const void* src) {
    asm volatile("cp.async.cg.shared.global [%0], [%1], 16;" :: "r"(dst), "l"(src));
}
#define CP_COMMIT() asm volatile("cp.async.commit_group;")
#define CP_WAIT0()  asm volatile("cp.async.wait_group 0;" ::: "memory")
#define CP_WAIT1()  asm volatile("cp.async.wait_group 1;" ::: "memory")

__device__ __forceinline__ void grid_barrier() {
    __syncthreads();
    if (threadIdx.x == 0) {
        __threadfence();
        unsigned gen = *(volatile unsigned*)&g_bar_gen;
        if (atomicAdd(&g_bar_count, 1u) == NBLK - 1) {
            g_bar_count = 0;
            __threadfence();
            atomicAdd(&g_bar_gen, 1u);
        } else {
            while (*(volatile unsigned*)&g_bar_gen == gen) { __nanosleep(64); }
        }
        __threadfence();
    }
    __syncthreads();
}

// ---------------- weight precompute (identical layout to R14) -------------------
__device__ void prep_w(uint32_t* dst, const float* W, long idx, int NCH, int K) {
    int nt = (int)(idx / ((long)NCH * 8192));
    int r  = (int)(idx % ((long)NCH * 8192));
    int ch = r / 8192, g = r % 8192;
    int u = g >> 2, w4 = g & 3;
    int sp = u >> 10, col = (u >> 2) & 255, qx = u & 3;
    int q = qx ^ ((col >> 1) & 3);
    int k = ch * 64 + (sp * 2 + (w4 >> 1)) * 16 + 2 * (q + 4 * (w4 & 1));
    int gate = col & 3;
    int wcol = gate * HDIM + nt * 64 + (col >> 2);
    float lo = (k     < K) ? W[(size_t)k * (4 * HDIM) + wcol] : 0.0f;
    float hf = (k + 1 < K) ? W[(size_t)(k + 1) * (4 * HDIM) + wcol] : 0.0f;
    dst[idx] = f2h2(lo, hf);
}

__global__ void precompute_weights(const float* __restrict__ W0, const float* __restrict__ W1,
                                   const float* __restrict__ W2, const float* __restrict__ P0,
                                   const float* __restrict__ P1, const float* __restrict__ P2)
{
    long idx = (long)blockIdx.x * 256 + threadIdx.x;
    const long NW0  = 12L * NCH0  * 8192;
    const long NW12 = 12L * NCH12 * 8192;
    if (idx < NW0)  { prep_w(g_W0pre, W0, idx, NCH0, K0REAL); return; }
    idx -= NW0;
    if (idx < NW12) { prep_w(g_W1pre, W1, idx, NCH12, 512); return; }
    idx -= NW12;
    if (idx < NW12) { prep_w(g_W2pre, W2, idx, NCH12, 512); return; }
    idx -= NW12;
    if (idx < 3L * 4 * NCHP * 2048) {
        long save = idx;
        int layer = (int)(idx / (4 * NCHP * 2048));
        int r  = (int)(idx % (4 * NCHP * 2048));
        int nt4 = r / (NCHP * 2048);
        int r2  = r % (NCHP * 2048);
        int ch  = r2 / 2048, g = r2 % 2048;
        int u = g >> 2, w4 = g & 3;
        int sp = u >> 8, col = (u >> 2) & 63, qx = u & 3;
        int q = qx ^ ((col >> 1) & 3);
        int k = ch * 64 + (sp * 2 + (w4 >> 1)) * 16 + 2 * (q + 4 * (w4 & 1));
        int n = nt4 * 64 + col;
        const float* P = (layer == 0) ? P0 : (layer == 1) ? P1 : P2;
        g_Ppre[save] = f2h2(P[k * PJDIM + n], P[(k + 1) * PJDIM + n]);
    }
}

// ---------------- gates: 64x256 tile, 16 warps (warp tile 16x64) ----------------
// smem words: A bufs 3x2048 at [0,6144), W bufs 3x8192 at [6144, 30720)
template <int XK, int NCH>
__device__ void gates_tile(const float* __restrict__ xA,
                           const __half* __restrict__ h1,
                           const __half* __restrict__ h2,
                           const uint32_t* __restrict__ Wt,
                           const float* __restrict__ bias,
                           float* __restrict__ cbuf, __half* __restrict__ mbuf,
                           uint32_t* __restrict__ sm, uint32_t sb)
{
    const int tid = threadIdx.x, lane = tid & 31, wid = tid >> 5;
    const int bid = blockIdx.x;
    const int m0  = (bid % 10) * 64;
    const int nt0 = bid / 10;
    const int wm = wid >> 2, wn = wid & 3;          // 4 x 4 warps
    const int grp = lane >> 2, q = lane & 3;
    const int qx4 = ((lane & 3) ^ ((lane >> 3) & 3)) * 4;
    const int row = tid >> 3, aj = tid & 7;          // A fill: 1 ld8/thread
    const int xs  = (row >> 1) & 3;

    float acc[8][4];
#pragma unroll
    for (int nt = 0; nt < 8; nt++)
#pragma unroll
        for (int r = 0; r < 4; r++) acc[nt][r] = 0.0f;

    uint4 hv;
    auto ld8 = [&](int kg) -> uint4 {
        uint4 v;
        if (XK == 40) {
            if (kg < 40) {
                float4 f0 = __ldg((const float4*)&xA[(m0 + row) * 40 + kg]);
                float4 f1 = __ldg((const float4*)&xA[(m0 + row) * 40 + kg + 4]);
                v.x = f2h2(f0.x, f0.y); v.y = f2h2(f0.z, f0.w);
                v.z = f2h2(f1.x, f1.y); v.w = f2h2(f1.z, f1.w);
            } else if (kg < 296) {
                v = __ldcg((const uint4*)&h2[(m0 + row) * PJDIM + kg - 40]);
            } else {
                v = make_uint4(0u, 0u, 0u, 0u);
            }
        } else {
            if (kg < 256) v = __ldcg((const uint4*)&h1[(m0 + row) * PJDIM + kg]);
            else          v = __ldcg((const uint4*)&h2[(m0 + row) * PJDIM + kg - 256]);
        }
        return v;
    };
    auto ldA = [&](int ch) { hv = ld8(ch * 64 + aj * 8); };
    auto stA = [&](int buf) {
        int sp = aj >> 2, ajj = aj & 3;
        uint32_t* d = sm + buf * 2048 + sp * 1024 + row * 16 + (ajj >> 1) * 2 + (ajj & 1);
        d[(0 ^ xs) << 2] = hv.x; d[(1 ^ xs) << 2] = hv.y;
        d[(2 ^ xs) << 2] = hv.z; d[(3 ^ xs) << 2] = hv.w;
    };
    auto ldW = [&](int ch, int buf) {
        const uint32_t* src = Wt + (size_t)ch * 8192 + tid * 4;
        uint32_t dst = sb + (6144 + buf * 8192 + tid * 4) * 4;
#pragma unroll
        for (int e = 0; e < 4; e++) cp16(dst + e * 8192, src + e * 2048);
        CP_COMMIT();
    };

    ldA(0); stA(0); ldW(0, 0);
    ldA(1); stA(1); ldW(1, 1);

    for (int ch = 0; ch < NCH; ch++) {
        int buf = ch % 3;
        bool more = (ch + 2 < NCH);
        if (more) ldA(ch + 2);                 // LDG overlaps the cp wait
        if (ch <= NCH - 2) CP_WAIT1(); else CP_WAIT0();
        __syncthreads();

        const uint32_t* bA = sm + buf * 2048;
        const uint32_t* bW = sm + 6144 + buf * 8192;
#pragma unroll
        for (int sp = 0; sp < 2; sp++) {
            int r0 = wm * 16 + grp;
            uint4 A0 = *(const uint4*)&bA[sp * 1024 + r0 * 16 + qx4];
            uint4 A1 = *(const uint4*)&bA[sp * 1024 + (r0 + 8) * 16 + qx4];
#pragma unroll
            for (int nt = 0; nt < 8; nt++) {
                int col = wn * 64 + nt * 8 + grp;
                uint4 B = *(const uint4*)&bW[sp * 4096 + col * 16 + qx4];
                mma_f16(acc[nt][0], acc[nt][1], acc[nt][2], acc[nt][3],
                        A0.x, A1.x, A0.y, A1.y, B.x, B.y);
                mma_f16(acc[nt][0], acc[nt][1], acc[nt][2], acc[nt][3],
                        A0.z, A1.z, A0.w, A1.w, B.z, B.w);
            }
        }
        if (more) { stA((ch + 2) % 3); ldW(ch + 2, (ch + 2) % 3); }
    }

    // Epilogue: lane pair (lane^1) assembles (i,j,f,o) per cell column.
    const int gc0 = nt0 * 64;
    const int p = lane & 1;
#pragma unroll
    for (int nt = 0; nt < 8; nt++) {
        int cc = wn * 16 + 2 * nt + (q >> 1);
        int gc = gc0 + cc;
        float bi = __ldg(&bias[gc]);
        float bj = __ldg(&bias[gc + HDIM]);
        float bf = __ldg(&bias[gc + 2 * HDIM]);
        float bo = __ldg(&bias[gc + 3 * HDIM]);
        float c0 = acc[nt][0], c1 = acc[nt][1];
        float c2 = acc[nt][2], c3 = acc[nt][3];
        float v = __shfl_xor_sync(0xffffffffu, p ? c0 : c2, 1);
        float w = __shfl_xor_sync(0xffffffffu, p ? c1 : c3, 1);
        float zi, zj, zf, zo;
        if (p == 0) { zi = c0; zj = c1; zf = v;  zo = w;  }
        else        { zi = v;  zj = w;  zf = c2; zo = c3; }
        int rowE = m0 + wm * 16 + grp + (p ? 8 : 0);
        zi += bi; zj += bj; zf += bf; zo += bo;
        float cold = cbuf[gc * BATCH + rowE];
        float cn = sig_fast(zf + 1.0f) * cold + sig_fast(zi) * tanh_fast(zj);
        float mm = sig_fast(zo) * tanh_fast(cn);
        cbuf[gc * BATCH + rowE] = cn;
        mbuf[gc * BATCH + rowE] = __float2half(mm);
    }
}

// ---------------- projection: 64x64 tile, 16 warps (warp tile 16x16) ------------
// smem words: A bufs 3x2048 at [0,6144), W bufs 3x2048 at [6144,12288)
__device__ void proj_mma(const __half* __restrict__ mperm,
                         const uint32_t* __restrict__ Pblk,
                         float* __restrict__ hL, __half* __restrict__ hhL,
                         int m0, int nt4,
                         uint32_t* __restrict__ sm, uint32_t sb)
{
    const int tid = threadIdx.x, lane = tid & 31, wid = tid >> 5;
    const int wm = wid >> 2, wn = wid & 3;
    const int grp = lane >> 2, q = lane & 3;
    const int qx4 = ((lane & 3) ^ ((lane >> 3) & 3)) * 4;
    const int klocal = tid >> 3;           // 0..63
    const int row8 = (tid & 7) * 8;

    float acc[2][4];
#pragma unroll
    for (int nt = 0; nt < 2; nt++)
#pragma unroll
        for (int r = 0; r < 4; r++) acc[nt][r] = 0.0f;

    uint4 hv;
    auto ldA = [&](int ch) {
        hv = __ldcg((const uint4*)&mperm[(ch * 64 + klocal) * BATCH + m0 + row8]);
    };
    auto stA = [&](int buf) {   // R13 layout: word = s*512 + row*8 + pos^xr
        int kw = klocal >> 1, hsel = klocal & 1;
        int s = kw >> 3, kw8 = kw & 7;
        int pos = (kw8 & 3) * 2 + (kw8 >> 2);
        __half hs[8];
        *(uint32_t*)&hs[0] = hv.x; *(uint32_t*)&hs[2] = hv.y;
        *(uint32_t*)&hs[4] = hv.z; *(uint32_t*)&hs[6] = hv.w;
#pragma unroll
        for (int e = 0; e < 8; e++) {
            int rw = row8 + e;
            int xr = ((rw >> 3) & 3) << 1;
            __half* hp = (__half*)(sm + buf * 2048 + s * 512 + rw * 8 + (pos ^ xr));
            hp[hsel] = hs[e];
        }
    };
    auto ldW = [&](int ch, int buf) {
        cp16(sb + (6144 + buf * 2048 + tid * 4) * 4, Pblk + (size_t)ch * 2048 + tid * 4);
        CP_COMMIT();
    };

    ldA(0); stA(0); ldW(0, 0);
    ldA(1); stA(1); ldW(1, 1);

    for (int ch = 0; ch < NCHP; ch++) {
        int buf = ch % 3;
        bool more = (ch + 2 < NCHP);
        if (more) ldA(ch + 2);
        if (ch <= NCHP - 2) CP_WAIT1(); else CP_WAIT0();
        __syncthreads();

        const uint32_t* bA = sm + buf * 2048;
        const uint32_t* bW = sm + 6144 + buf * 2048;
#pragma unroll
        for (int sp = 0; sp < 2; sp++) {
            uint4 Bn[2];
#pragma unroll
            for (int nt = 0; nt < 2; nt++) {
                int col = wn * 16 + nt * 8 + grp;
                Bn[nt] = *(const uint4*)&bW[sp * 1024 + col * 16 + qx4];
            }
#pragma unroll
            for (int s01 = 0; s01 < 2; s01++) {
                int s = sp * 2 + s01;
                int r0 = wm * 16 + grp;
                int r1 = r0 + 8;
                int x0 = ((r0 >> 3) & 3) << 1;
                int x1 = ((r1 >> 3) & 3) << 1;
                uint2 a02 = *(const uint2*)&bA[s * 512 + r0 * 8 + ((q * 2) ^ x0)];
                uint2 a13 = *(const uint2*)&bA[s * 512 + r1 * 8 + ((q * 2) ^ x1)];
#pragma unroll
                for (int nt = 0; nt < 2; nt++) {
                    uint32_t b0 = s01 ? Bn[nt].z : Bn[nt].x;
                    uint32_t b1 = s01 ? Bn[nt].w : Bn[nt].y;
                    mma_f16(acc[nt][0], acc[nt][1], acc[nt][2], acc[nt][3],
                            a02.x, a13.x, a02.y, a13.y, b0, b1);
                }
            }
        }
        if (more) { stA((ch + 2) % 3); ldW(ch + 2, (ch + 2) % 3); }
    }

#pragma unroll
    for (int nt = 0; nt < 2; nt++) {
        int rw = m0 + wm * 16 + grp;
        int col = nt4 * 64 + wn * 16 + nt * 8 + 2 * q;
        *(float2*)&hL[rw * PJDIM + col] = make_float2(acc[nt][0], acc[nt][1]);
        *(float2*)&hL[(rw + 8) * PJDIM + col] = make_float2(acc[nt][2], acc[nt][3]);
        *(uint32_t*)&hhL[rw * PJDIM + col] = f2h2(acc[nt][0], acc[nt][1]);
        *(uint32_t*)&hhL[(rw + 8) * PJDIM + col] = f2h2(acc[nt][2], acc[nt][3]);
    }
}

// ---------------- persistent driver ----------------------------------------------
__global__ void __launch_bounds__(NTHR, 1)
lstm_persistent(const float* __restrict__ x,
                const float* __restrict__ b0, const float* __restrict__ b1,
                const float* __restrict__ b2, float* __restrict__ out)
{
    extern __shared__ uint32_t dynsmem[];   // 30720 words = 120KB
    __shared__ float red[16];
    uint32_t* sm = dynsmem;
    uint32_t sb = (uint32_t)__cvta_generic_to_shared(dynsmem);

    const int bid = blockIdx.x;
    const int tid = threadIdx.x;

    for (int i = bid * NTHR + tid; i < 3 * HDIM * BATCH; i += NBLK * NTHR)
        ((float*)g_c)[i] = 0.0f;
    for (int i = bid * NTHR + tid; i < 3 * BATCH * PJDIM / 2; i += NBLK * NTHR)
        ((uint32_t*)g_hh)[i] = 0u;
    for (int i = bid * NTHR + tid; i < 3 * BATCH * PJDIM; i += NBLK * NTHR)
        ((float*)g_h)[i] = 0.0f;
    grid_barrier();

    const int g_nt = bid / 10;
    const uint32_t* W0t = g_W0pre + (size_t)g_nt * NCH0  * 8192;
    const uint32_t* W1t = g_W1pre + (size_t)g_nt * NCH12 * 8192;
    const uint32_t* W2t = g_W2pre + (size_t)g_nt * NCH12 * 8192;

    const int p_layer = bid / 40, p_rem = bid % 40;
    const int p_m0 = (p_rem % 10) * 64, p_nt4 = p_rem / 10;
    const uint32_t* Pblk = g_Ppre + ((size_t)p_layer * 4 + p_nt4) * NCHP * 2048;

    for (int s = 0; s < T_STEPS + 2; s++) {
        if (s < T_STEPS)
            gates_tile<40, NCH0>(x + (size_t)s * BATCH * FDIM, (const __half*)nullptr,
                                 g_hh[0], W0t, b0, g_c[0], g_m[0], sm, sb);
        if (s >= 1 && s - 1 < T_STEPS)
            gates_tile<256, NCH12>(nullptr, g_hh[0], g_hh[1], W1t, b1,
                                   g_c[1], g_m[1], sm, sb);
        if (s >= 2 && s - 2 < T_STEPS)
            gates_tile<256, NCH12>(nullptr, g_hh[1], g_hh[2], W2t, b2,
                                   g_c[2], g_m[2], sm, sb);
        grid_barrier();

        if (s - p_layer >= 0 && s - p_layer < T_STEPS)
            proj_mma(g_m[p_layer], Pblk, g_h[p_layer], g_hh[p_layer],
                     p_m0, p_nt4, sm, sb);
        grid_barrier();
    }

    // L2 normalize: 512 threads handle 2 batches/block-pass (warps 0-7 / 8-15).
    const int half = tid >> 8;        // 0 or 1
    const int t    = tid & 255;
    for (int bb = bid; bb < BATCH / 2; bb += NBLK) {
        int b = bb * 2 + half;
        float v = __ldcg(&g_h[2][b * PJDIM + t]);
        float sm2 = v * v;
#pragma unroll
        for (int o = 16; o > 0; o >>= 1) sm2 += __shfl_xor_sync(0xffffffffu, sm2, o);
        if ((tid & 31) == 0) red[tid >> 5] = sm2;
        __syncthreads();
        float tot = 0.0f;
#pragma unroll
        for (int wv = 0; wv < 8; wv++) tot += red[half * 8 + wv];
        out[b * PJDIM + t] = v * rsqrtf(fmaxf(tot, 1e-12f));
        __syncthreads();
    }
}

extern "C" void kernel_launch(void* const* d_in, const int* in_sizes, int n_in,
                              void* d_out, int out_size)
{
    const float* x  = (const float*)d_in[0];
    const float* W0 = (const float*)d_in[1];
    const float* b0 = (const float*)d_in[2];
    const float* P0 = (const float*)d_in[3];
    const float* W1 = (const float*)d_in[4];
    const float* b1 = (const float*)d_in[5];
    const float* P1 = (const float*)d_in[6];
    const float* W2 = (const float*)d_in[7];
    const float* b2 = (const float*)d_in[8];
    const float* P2 = (const float*)d_in[9];
    float* out = (float*)d_out;
    (void)in_sizes; (void)n_in; (void)out_size;

    static int attr_done = 0;
    if (!attr_done) {
        cudaFuncSetAttribute(lstm_persistent,
                             cudaFuncAttributeMaxDynamicSharedMemorySize, 122880);
        attr_done = 1;
    }

    precompute_weights<<<9216, 256>>>(W0, W1, W2, P0, P1, P2);
    lstm_persistent<<<NBLK, NTHR, 122880>>>(x, b0, b1, b2, out);
}

// round 16
// speedup vs baseline: 1.2547x; 1.0394x over previous
#include <cuda_runtime.h>
#include <cuda_fp16.h>
#include <math.h>
#include <stdint.h>

#define T_STEPS 160
#define BATCH   640
#define FDIM    40
#define HDIM    768
#define PJDIM   256
#define NBLK    120
#define NTHR    512

#define NCH0    5      // gates L0: K=296 padded to 320, chunks of 64
#define NCH12   8      // gates L1/2: K=512
#define NCHP    12     // proj: K=768
#define K0REAL  296

// ---------------- device globals ----------------------------------------------
__device__ float  g_c[3][HDIM * BATCH];     // fp32 cell, permuted [gc*640+row]
__device__ __half g_m[3][HDIM * BATCH];     // fp16 m, permuted [gc*640+row]
__device__ __half g_hh[3][BATCH * PJDIM];   // fp16 h, row-major
__device__ float  g_h[3][BATCH * PJDIM];    // fp32 h (final norm)
__device__ unsigned g_bar_count;
__device__ unsigned g_bar_gen;

// Pre-swizzled fp16 weights, gmem order == smem order (paired-k LDS.128 layout).
__device__ uint32_t g_W0pre[12 * NCH0  * 8192];
__device__ uint32_t g_W1pre[12 * NCH12 * 8192];
__device__ uint32_t g_W2pre[12 * NCH12 * 8192];
__device__ uint32_t g_Ppre [3 * 4 * NCHP * 2048];

__device__ __forceinline__ float sig_fast(float x) {
    float e = __expf(-x);
    float r; asm("rcp.approx.f32 %0, %1;" : "=f"(r) : "f"(1.0f + e));
    return r;
}
__device__ __forceinline__ float tanh_fast(float x) {
    float e = __expf(-2.0f * x);
    float r; asm("rcp.approx.f32 %0, %1;" : "=f"(r) : "f"(1.0f + e));
    return 2.0f * r - 1.0f;
}

__device__ __forceinline__ uint32_t f2h2(float a, float b) {
    __half2 h = __floats2half2_rn(a, b);
    return *(uint32_t*)&h;
}

__device__ __forceinline__ void mma_f16(float& c0, float& c1, float& c2, float& c3,
                                        uint32_t a0, uint32_t a1, uint32_t a2, uint32_t a3,
                                        uint32_t b0, uint32_t b1) {
    asm("mma.sync.aligned.m16n8k16.row.col.f32.f16.f16.f32 "
        "{%0,%1,%2,%3},{%4,%5,%6,%7},{%8,%9},{%0,%1,%2,%3};"
        : "+f"(c0), "+f"(c1), "+f"(c2), "+f"(c3)
        : "r"(a0), "r"(a1), "r"(a2), "r"(a3), "r"(b0), "r"(b1));
}

__device__ __forceinline__ void cp16(uint32_t dst, const void* src) {
    asm volatile("cp.async.cg.shared.global [%0], [%1], 16;" :: "r"(dst), "l"(src));
}
#define CP_COMMIT() asm volatile("cp.async.commit_group;")
#define CP_WAIT0()  asm volatile("cp.async.wait_group 0;" ::: "memory")
#define CP_WAIT1()  asm volatile("cp.async.wait_group 1;" ::: "memory")

__device__ __forceinline__ void grid_barrier() {
    __syncthreads();
    if (threadIdx.x == 0) {
        __threadfence();
        unsigned gen = *(volatile unsigned*)&g_bar_gen;
        if (atomicAdd(&g_bar_count, 1u) == NBLK - 1) {
            g_bar_count = 0;
            __threadfence();
            atomicAdd(&g_bar_gen, 1u);
        } else {
            while (*(volatile unsigned*)&g_bar_gen == gen) { __nanosleep(64); }
        }
        __threadfence();
    }
    __syncthreads();
}

// ---------------- weight precompute (identical layout to R14/R15) ---------------
__device__ void prep_w(uint32_t* dst, const float* W, long idx, int NCH, int K) {
    int nt = (int)(idx / ((long)NCH * 8192));
    int r  = (int)(idx % ((long)NCH * 8192));
    int ch = r / 8192, g = r % 8192;
    int u = g >> 2, w4 = g & 3;
    int sp = u >> 10, col = (u >> 2) & 255, qx = u & 3;
    int q = qx ^ ((col >> 1) & 3);
    int k = ch * 64 + (sp * 2 + (w4 >> 1)) * 16 + 2 * (q + 4 * (w4 & 1));
    int gate = col & 3;
    int wcol = gate * HDIM + nt * 64 + (col >> 2);
    float lo = (k     < K) ? W[(size_t)k * (4 * HDIM) + wcol] : 0.0f;
    float hf = (k + 1 < K) ? W[(size_t)(k + 1) * (4 * HDIM) + wcol] : 0.0f;
    dst[idx] = f2h2(lo, hf);
}

__global__ void precompute_weights(const float* __restrict__ W0, const float* __restrict__ W1,
                                   const float* __restrict__ W2, const float* __restrict__ P0,
                                   const float* __restrict__ P1, const float* __restrict__ P2)
{
    long idx = (long)blockIdx.x * 256 + threadIdx.x;
    const long NW0  = 12L * NCH0  * 8192;
    const long NW12 = 12L * NCH12 * 8192;
    if (idx < NW0)  { prep_w(g_W0pre, W0, idx, NCH0, K0REAL); return; }
    idx -= NW0;
    if (idx < NW12) { prep_w(g_W1pre, W1, idx, NCH12, 512); return; }
    idx -= NW12;
    if (idx < NW12) { prep_w(g_W2pre, W2, idx, NCH12, 512); return; }
    idx -= NW12;
    if (idx < 3L * 4 * NCHP * 2048) {
        long save = idx;
        int layer = (int)(idx / (4 * NCHP * 2048));
        int r  = (int)(idx % (4 * NCHP * 2048));
        int nt4 = r / (NCHP * 2048);
        int r2  = r % (NCHP * 2048);
        int ch  = r2 / 2048, g = r2 % 2048;
        int u = g >> 2, w4 = g & 3;
        int sp = u >> 8, col = (u >> 2) & 63, qx = u & 3;
        int q = qx ^ ((col >> 1) & 3);
        int k = ch * 64 + (sp * 2 + (w4 >> 1)) * 16 + 2 * (q + 4 * (w4 & 1));
        int n = nt4 * 64 + col;
        const float* P = (layer == 0) ? P0 : (layer == 1) ? P1 : P2;
        g_Ppre[save] = f2h2(P[k * PJDIM + n], P[(k + 1) * PJDIM + n]);
    }
}

// ---------------- gates: 64x256 tile, 16 warps (warp tile 32x32) ----------------
// smem words: A bufs 3x2048 at [0,6144), W bufs 3x8192 at [6144, 30720)
template <int XK, int NCH>
__device__ void gates_tile(const float* __restrict__ xA,
                           const __half* __restrict__ h1,
                           const __half* __restrict__ h2,
                           const uint32_t* __restrict__ Wt,
                           const float* __restrict__ bias,
                           float* __restrict__ cbuf, __half* __restrict__ mbuf,
                           uint32_t* __restrict__ sm, uint32_t sb)
{
    const int tid = threadIdx.x, lane = tid & 31, wid = tid >> 5;
    const int bid = blockIdx.x;
    const int m0  = (bid % 10) * 64;
    const int nt0 = bid / 10;
    const int wm = wid >> 3, wn = wid & 7;          // 2 x 8 warps, tile 32x32
    const int grp = lane >> 2, q = lane & 3;
    const int qx4 = ((lane & 3) ^ ((lane >> 3) & 3)) * 4;
    const int row = tid >> 3, aj = tid & 7;          // A fill: 1 ld8/thread
    const int xs  = (row >> 1) & 3;

    float acc[2][4][4];
#pragma unroll
    for (int mt = 0; mt < 2; mt++)
#pragma unroll
        for (int nt = 0; nt < 4; nt++)
#pragma unroll
            for (int r = 0; r < 4; r++) acc[mt][nt][r] = 0.0f;

    uint4 hv;
    auto ld8 = [&](int kg) -> uint4 {
        uint4 v;
        if (XK == 40) {
            if (kg < 40) {
                float4 f0 = __ldg((const float4*)&xA[(m0 + row) * 40 + kg]);
                float4 f1 = __ldg((const float4*)&xA[(m0 + row) * 40 + kg + 4]);
                v.x = f2h2(f0.x, f0.y); v.y = f2h2(f0.z, f0.w);
                v.z = f2h2(f1.x, f1.y); v.w = f2h2(f1.z, f1.w);
            } else if (kg < 296) {
                v = __ldcg((const uint4*)&h2[(m0 + row) * PJDIM + kg - 40]);
            } else {
                v = make_uint4(0u, 0u, 0u, 0u);
            }
        } else {
            if (kg < 256) v = __ldcg((const uint4*)&h1[(m0 + row) * PJDIM + kg]);
            else          v = __ldcg((const uint4*)&h2[(m0 + row) * PJDIM + kg - 256]);
        }
        return v;
    };
    auto ldA = [&](int ch) { hv = ld8(ch * 64 + aj * 8); };
    auto stA = [&](int buf) {
        int sp = aj >> 2, ajj = aj & 3;
        uint32_t* d = sm + buf * 2048 + sp * 1024 + row * 16 + (ajj >> 1) * 2 + (ajj & 1);
        d[(0 ^ xs) << 2] = hv.x; d[(1 ^ xs) << 2] = hv.y;
        d[(2 ^ xs) << 2] = hv.z; d[(3 ^ xs) << 2] = hv.w;
    };
    auto ldW = [&](int ch, int buf) {
        const uint32_t* src = Wt + (size_t)ch * 8192 + tid * 4;
        uint32_t dst = sb + (6144 + buf * 8192 + tid * 4) * 4;
#pragma unroll
        for (int e = 0; e < 4; e++) cp16(dst + e * 8192, src + e * 2048);
        CP_COMMIT();
    };

    ldA(0); stA(0); ldW(0, 0);
    ldA(1); stA(1); ldW(1, 1);

    for (int ch = 0; ch < NCH; ch++) {
        int buf = ch % 3;
        bool more = (ch + 2 < NCH);
        if (more) ldA(ch + 2);                 // LDG overlaps the cp wait
        if (ch <= NCH - 2) CP_WAIT1(); else CP_WAIT0();
        __syncthreads();

        const uint32_t* bA = sm + buf * 2048;
        const uint32_t* bW = sm + 6144 + buf * 8192;
#pragma unroll
        for (int sp = 0; sp < 2; sp++) {
            uint4 A0[2], A1[2];
#pragma unroll
            for (int mt = 0; mt < 2; mt++) {
                int r0 = wm * 32 + mt * 16 + grp;
                A0[mt] = *(const uint4*)&bA[sp * 1024 + r0 * 16 + qx4];
                A1[mt] = *(const uint4*)&bA[sp * 1024 + (r0 + 8) * 16 + qx4];
            }
#pragma unroll
            for (int nt = 0; nt < 4; nt++) {
                int col = wn * 32 + nt * 8 + grp;
                uint4 B = *(const uint4*)&bW[sp * 4096 + col * 16 + qx4];
#pragma unroll
                for (int mt = 0; mt < 2; mt++) {
                    mma_f16(acc[mt][nt][0], acc[mt][nt][1], acc[mt][nt][2], acc[mt][nt][3],
                            A0[mt].x, A1[mt].x, A0[mt].y, A1[mt].y, B.x, B.y);
                    mma_f16(acc[mt][nt][0], acc[mt][nt][1], acc[mt][nt][2], acc[mt][nt][3],
                            A0[mt].z, A1[mt].z, A0[mt].w, A1[mt].w, B.z, B.w);
                }
            }
        }
        if (more) { stA((ch + 2) % 3); ldW(ch + 2, (ch + 2) % 3); }
    }

    // Epilogue: lane pair (lane^1) assembles (i,j,f,o) per cell column.
    const int gc0 = nt0 * 64;
    const int p = lane & 1;
#pragma unroll
    for (int nt = 0; nt < 4; nt++) {
        int cc = wn * 8 + 2 * nt + (q >> 1);
        int gc = gc0 + cc;
        float bi = __ldg(&bias[gc]);
        float bj = __ldg(&bias[gc + HDIM]);
        float bf = __ldg(&bias[gc + 2 * HDIM]);
        float bo = __ldg(&bias[gc + 3 * HDIM]);
#pragma unroll
        for (int mt = 0; mt < 2; mt++) {
            float c0 = acc[mt][nt][0], c1 = acc[mt][nt][1];
            float c2 = acc[mt][nt][2], c3 = acc[mt][nt][3];
            float v = __shfl_xor_sync(0xffffffffu, p ? c0 : c2, 1);
            float w = __shfl_xor_sync(0xffffffffu, p ? c1 : c3, 1);
            float zi, zj, zf, zo;
            if (p == 0) { zi = c0; zj = c1; zf = v;  zo = w;  }
            else        { zi = v;  zj = w;  zf = c2; zo = c3; }
            int rowE = m0 + wm * 32 + mt * 16 + grp + (p ? 8 : 0);
            zi += bi; zj += bj; zf += bf; zo += bo;
            float cold = cbuf[gc * BATCH + rowE];
            float cn = sig_fast(zf + 1.0f) * cold + sig_fast(zi) * tanh_fast(zj);
            float mm = sig_fast(zo) * tanh_fast(cn);
            cbuf[gc * BATCH + rowE] = cn;
            mbuf[gc * BATCH + rowE] = __float2half(mm);
        }
    }
}

// ---------------- projection: 64x64 tile, 16 warps (warp tile 16x16) ------------
// smem words: A bufs 3x2048 at [0,6144), W bufs 3x2048 at [6144,12288)
__device__ void proj_mma(const __half* __restrict__ mperm,
                         const uint32_t* __restrict__ Pblk,
                         float* __restrict__ hL, __half* __restrict__ hhL,
                         int m0, int nt4,
                         uint32_t* __restrict__ sm, uint32_t sb)
{
    const int tid = threadIdx.x, lane = tid & 31, wid = tid >> 5;
    const int wm = wid >> 2, wn = wid & 3;
    const int grp = lane >> 2, q = lane & 3;
    const int qx4 = ((lane & 3) ^ ((lane >> 3) & 3)) * 4;
    const int klocal = tid >> 3;           // 0..63
    const int row8 = (tid & 7) * 8;

    float acc[2][4];
#pragma unroll
    for (int nt = 0; nt < 2; nt++)
#pragma unroll
        for (int r = 0; r < 4; r++) acc[nt][r] = 0.0f;

    uint4 hv;
    auto ldA = [&](int ch) {
        hv = __ldcg((const uint4*)&mperm[(ch * 64 + klocal) * BATCH + m0 + row8]);
    };
    auto stA = [&](int buf) {   // R13 layout: word = s*512 + row*8 + pos^xr
        int kw = klocal >> 1, hsel = klocal & 1;
        int s = kw >> 3, kw8 = kw & 7;
        int pos = (kw8 & 3) * 2 + (kw8 >> 2);
        __half hs[8];
        *(uint32_t*)&hs[0] = hv.x; *(uint32_t*)&hs[2] = hv.y;
        *(uint32_t*)&hs[4] = hv.z; *(uint32_t*)&hs[6] = hv.w;
#pragma unroll
        for (int e = 0; e < 8; e++) {
            int rw = row8 + e;
            int xr = ((rw >> 3) & 3) << 1;
            __half* hp = (__half*)(sm + buf * 2048 + s * 512 + rw * 8 + (pos ^ xr));
            hp[hsel] = hs[e];
        }
    };
    auto ldW = [&](int ch, int buf) {
        cp16(sb + (6144 + buf * 2048 + tid * 4) * 4, Pblk + (size_t)ch * 2048 + tid * 4);
        CP_COMMIT();
    };

    ldA(0); stA(0); ldW(0, 0);
    ldA(1); stA(1); ldW(1, 1);

    for (int ch = 0; ch < NCHP; ch++) {
        int buf = ch % 3;
        bool more = (ch + 2 < NCHP);
        if (more) ldA(ch + 2);
        if (ch <= NCHP - 2) CP_WAIT1(); else CP_WAIT0();
        __syncthreads();

        const uint32_t* bA = sm + buf * 2048;
        const uint32_t* bW = sm + 6144 + buf * 2048;
#pragma unroll
        for (int sp = 0; sp < 2; sp++) {
            uint4 Bn[2];
#pragma unroll
            for (int nt = 0; nt < 2; nt++) {
                int col = wn * 16 + nt * 8 + grp;
                Bn[nt] = *(const uint4*)&bW[sp * 1024 + col * 16 + qx4];
            }
#pragma unroll
            for (int s01 = 0; s01 < 2; s01++) {
                int s = sp * 2 + s01;
                int r0 = wm * 16 + grp;
                int r1 = r0 + 8;
                int x0 = ((r0 >> 3) & 3) << 1;
                int x1 = ((r1 >> 3) & 3) << 1;
                uint2 a02 = *(const uint2*)&bA[s * 512 + r0 * 8 + ((q * 2) ^ x0)];
                uint2 a13 = *(const uint2*)&bA[s * 512 + r1 * 8 + ((q * 2) ^ x1)];
#pragma unroll
                for (int nt = 0; nt < 2; nt++) {
                    uint32_t b0 = s01 ? Bn[nt].z : Bn[nt].x;
                    uint32_t b1 = s01 ? Bn[nt].w : Bn[nt].y;
                    mma_f16(acc[nt][0], acc[nt][1], acc[nt][2], acc[nt][3],
                            a02.x, a13.x, a02.y, a13.y, b0, b1);
                }
            }
        }
        if (more) { stA((ch + 2) % 3); ldW(ch + 2, (ch + 2) % 3); }
    }

#pragma unroll
    for (int nt = 0; nt < 2; nt++) {
        int rw = m0 + wm * 16 + grp;
        int col = nt4 * 64 + wn * 16 + nt * 8 + 2 * q;
        *(float2*)&hL[rw * PJDIM + col] = make_float2(acc[nt][0], acc[nt][1]);
        *(float2*)&hL[(rw + 8) * PJDIM + col] = make_float2(acc[nt][2], acc[nt][3]);
        *(uint32_t*)&hhL[rw * PJDIM + col] = f2h2(acc[nt][0], acc[nt][1]);
        *(uint32_t*)&hhL[(rw + 8) * PJDIM + col] = f2h2(acc[nt][2], acc[nt][3]);
    }
}

// ---------------- persistent driver ----------------------------------------------
__global__ void __launch_bounds__(NTHR, 1)
lstm_persistent(const float* __restrict__ x,
                const float* __restrict__ b0, const float* __restrict__ b1,
                const float* __restrict__ b2, float* __restrict__ out)
{
    extern __shared__ uint32_t dynsmem[];   // 30720 words = 120KB
    __shared__ float red[16];
    uint32_t* sm = dynsmem;
    uint32_t sb = (uint32_t)__cvta_generic_to_shared(dynsmem);

    const int bid = blockIdx.x;
    const int tid = threadIdx.x;

    for (int i = bid * NTHR + tid; i < 3 * HDIM * BATCH; i += NBLK * NTHR)
        ((float*)g_c)[i] = 0.0f;
    for (int i = bid * NTHR + tid; i < 3 * BATCH * PJDIM / 2; i += NBLK * NTHR)
        ((uint32_t*)g_hh)[i] = 0u;
    for (int i = bid * NTHR + tid; i < 3 * BATCH * PJDIM; i += NBLK * NTHR)
        ((float*)g_h)[i] = 0.0f;
    grid_barrier();

    const int g_nt = bid / 10;
    const uint32_t* W0t = g_W0pre + (size_t)g_nt * NCH0  * 8192;
    const uint32_t* W1t = g_W1pre + (size_t)g_nt * NCH12 * 8192;
    const uint32_t* W2t = g_W2pre + (size_t)g_nt * NCH12 * 8192;

    const int p_layer = bid / 40, p_rem = bid % 40;
    const int p_m0 = (p_rem % 10) * 64, p_nt4 = p_rem / 10;
    const uint32_t* Pblk = g_Ppre + ((size_t)p_layer * 4 + p_nt4) * NCHP * 2048;

    for (int s = 0; s < T_STEPS + 2; s++) {
        if (s < T_STEPS)
            gates_tile<40, NCH0>(x + (size_t)s * BATCH * FDIM, (const __half*)nullptr,
                                 g_hh[0], W0t, b0, g_c[0], g_m[0], sm, sb);
        if (s >= 1 && s - 1 < T_STEPS)
            gates_tile<256, NCH12>(nullptr, g_hh[0], g_hh[1], W1t, b1,
                                   g_c[1], g_m[1], sm, sb);
        if (s >= 2 && s - 2 < T_STEPS)
            gates_tile<256, NCH12>(nullptr, g_hh[1], g_hh[2], W2t, b2,
                                   g_c[2], g_m[2], sm, sb);
        grid_barrier();

        if (s - p_layer >= 0 && s - p_layer < T_STEPS)
            proj_mma(g_m[p_layer], Pblk, g_h[p_layer], g_hh[p_layer],
                     p_m0, p_nt4, sm, sb);
        grid_barrier();
    }

    // L2 normalize: 512 threads handle 2 batches/block-pass (warps 0-7 / 8-15).
    const int half = tid >> 8;        // 0 or 1
    const int t    = tid & 255;
    for (int bb = bid; bb < BATCH / 2; bb += NBLK) {
        int b = bb * 2 + half;
        float v = __ldcg(&g_h[2][b * PJDIM + t]);
        float sm2 = v * v;
#pragma unroll
        for (int o = 16; o > 0; o >>= 1) sm2 += __shfl_xor_sync(0xffffffffu, sm2, o);
        if ((tid & 31) == 0) red[tid >> 5] = sm2;
        __syncthreads();
        float tot = 0.0f;
#pragma unroll
        for (int wv = 0; wv < 8; wv++) tot += red[half * 8 + wv];
        out[b * PJDIM + t] = v * rsqrtf(fmaxf(tot, 1e-12f));
        __syncthreads();
    }
}

extern "C" void kernel_launch(void* const* d_in, const int* in_sizes, int n_in,
                              void* d_out, int out_size)
{
    const float* x  = (const float*)d_in[0];
    const float* W0 = (const float*)d_in[1];
    const float* b0 = (const float*)d_in[2];
    const float* P0 = (const float*)d_in[3];
    const float* W1 = (const float*)d_in[4];
    const float* b1 = (const float*)d_in[5];
    const float* P1 = (const float*)d_in[6];
    const float* W2 = (const float*)d_in[7];
    const float* b2 = (const float*)d_in[8];
    const float* P2 = (const float*)d_in[9];
    float* out = (float*)d_out;
    (void)in_sizes; (void)n_in; (void)out_size;

    static int attr_done = 0;
    if (!attr_done) {
        cudaFuncSetAttribute(lstm_persistent,
                             cudaFuncAttributeMaxDynamicSharedMemorySize, 122880);
        attr_done = 1;
    }

    precompute_weights<<<9216, 256>>>(W0, W1, W2, P0, P1, P2);
    lstm_persistent<<<NBLK, NTHR, 122880>>>(x, b0, b1, b2, out);
}